// round 1
// baseline (speedup 1.0000x reference)
#include <cuda_runtime.h>
#include <math_constants.h>

// Problem constants
#define BATCH 4
#define SEQ   2048
#define EMB   1024
#define KD    1024

#define BM 128
#define BN 128
#define BK 16
#define LDSS 132   // BM + 4 pad: float4-aligned, near-conflict-free

// Static device scratch (allocation-free rule: __device__ globals are the workaround)
__device__ float g_Q[BATCH * SEQ * KD];            // 32 MB
__device__ float g_K[BATCH * SEQ * KD];            // 32 MB
__device__ float g_V[BATCH * SEQ * EMB];           // 32 MB
__device__ float g_P[(long long)BATCH * SEQ * SEQ]; // 64 MB (scores, then probs)

// C[m,n] = alpha * sum_k A[m,k] * Bop[k,n]
// TRANS_B = true : Bop[k,n] = B[n,k]  (B row-major [N,K])   -> NT GEMM
// TRANS_B = false: Bop[k,n] = B[k,n]  (B row-major [K,N])   -> NN GEMM
template<bool TRANS_B>
__device__ __forceinline__ void gemm_tile(
    const float* __restrict__ A, const float* __restrict__ B, float* __restrict__ C,
    int lda, int ldb, int ldc,
    int m0, int n0, int kEnd, float alpha)
{
    __shared__ __align__(16) float As[BK][LDSS];
    __shared__ __align__(16) float Bs[BK][LDSS];

    const int tid = threadIdx.x;
    const int tx = tid & 15;        // 0..15 -> column group
    const int ty = tid >> 4;        // 0..15 -> row group

    float acc[8][8];
    #pragma unroll
    for (int i = 0; i < 8; i++)
        #pragma unroll
        for (int j = 0; j < 8; j++) acc[i][j] = 0.0f;

    for (int k0 = 0; k0 < kEnd; k0 += BK) {
        // ---- load A tile [BM x BK], store transposed As[k][m] ----
        #pragma unroll
        for (int l = 0; l < 2; l++) {
            int f = tid + l * 256;           // float4 index, 512 total
            int row = f >> 2;                // 0..127
            int c4  = (f & 3) << 2;          // 0,4,8,12
            float4 v = *(const float4*)&A[(long long)(m0 + row) * lda + k0 + c4];
            As[c4 + 0][row] = v.x;
            As[c4 + 1][row] = v.y;
            As[c4 + 2][row] = v.z;
            As[c4 + 3][row] = v.w;
        }
        // ---- load B tile, store Bs[k][n] ----
        if (TRANS_B) {
            #pragma unroll
            for (int l = 0; l < 2; l++) {
                int f = tid + l * 256;
                int row = f >> 2;            // n index 0..127
                int c4  = (f & 3) << 2;      // k offset
                float4 v = *(const float4*)&B[(long long)(n0 + row) * ldb + k0 + c4];
                Bs[c4 + 0][row] = v.x;
                Bs[c4 + 1][row] = v.y;
                Bs[c4 + 2][row] = v.z;
                Bs[c4 + 3][row] = v.w;
            }
        } else {
            #pragma unroll
            for (int l = 0; l < 2; l++) {
                int f = tid + l * 256;
                int krow = f >> 5;           // 0..15
                int c4   = (f & 31) << 2;    // 0..124 step 4
                float4 v = *(const float4*)&B[(long long)(k0 + krow) * ldb + n0 + c4];
                *(float4*)&Bs[krow][c4] = v;
            }
        }
        __syncthreads();

        // ---- compute ----
        #pragma unroll
        for (int kk = 0; kk < BK; kk++) {
            float a[8], b[8];
            *(float4*)&a[0] = *(const float4*)&As[kk][ty * 4];
            *(float4*)&a[4] = *(const float4*)&As[kk][64 + ty * 4];
            *(float4*)&b[0] = *(const float4*)&Bs[kk][tx * 4];
            *(float4*)&b[4] = *(const float4*)&Bs[kk][64 + tx * 4];
            #pragma unroll
            for (int i = 0; i < 8; i++)
                #pragma unroll
                for (int j = 0; j < 8; j++)
                    acc[i][j] += a[i] * b[j];
        }
        __syncthreads();
    }

    // ---- epilogue ----
    #pragma unroll
    for (int i = 0; i < 8; i++) {
        int r = m0 + ((i < 4) ? (ty * 4 + i) : (64 + ty * 4 + (i - 4)));
        #pragma unroll
        for (int jj = 0; jj < 2; jj++) {
            float4 v;
            v.x = acc[i][jj * 4 + 0] * alpha;
            v.y = acc[i][jj * 4 + 1] * alpha;
            v.z = acc[i][jj * 4 + 2] * alpha;
            v.w = acc[i][jj * 4 + 3] * alpha;
            int c = n0 + tx * 4 + jj * 64;
            *(float4*)&C[(long long)r * ldc + c] = v;
        }
    }
}

// ---------------- kernels ----------------

// grid (N/128=8, M/128=64, 3), block 256
__global__ __launch_bounds__(256, 2)
void proj_kernel(const float* __restrict__ x,
                 const float* __restrict__ Wq,
                 const float* __restrict__ Wk,
                 const float* __restrict__ Wv)
{
    int z = blockIdx.z;
    const float* W = (z == 0) ? Wq : (z == 1) ? Wk : Wv;
    float* C = (z == 0) ? g_Q : (z == 1) ? g_K : g_V;
    gemm_tile<true>(x, W, C, EMB, EMB, KD,
                    blockIdx.y * BM, blockIdx.x * BN, EMB, 1.0f);
}

// grid (S/128=16, S/128=16, B=4): x = key tile, y = query tile
__global__ __launch_bounds__(256, 2)
void scores_kernel()
{
    int b = blockIdx.z;
    int bq = blockIdx.y, bs = blockIdx.x;
    if (bs > bq) return;  // strictly-upper tiles never read by softmax
    const float* Qb = g_Q + (long long)b * SEQ * KD;
    const float* Kb = g_K + (long long)b * SEQ * KD;
    float* Pb = g_P + (long long)b * SEQ * SEQ;
    gemm_tile<true>(Qb, Kb, Pb, KD, KD, SEQ,
                    bq * BM, bs * BN, KD, 0.03125f);  // 1/sqrt(1024)
}

// grid (SEQ, BATCH), block 256: causal row softmax, zero the masked tail
__global__ __launch_bounds__(256)
void softmax_kernel()
{
    int b = blockIdx.y, q = blockIdx.x;
    float* row = g_P + ((long long)b * SEQ + q) * SEQ;
    int n = q + 1;
    int tid = threadIdx.x;
    __shared__ float red[256];

    float m = -CUDART_INF_F;
    for (int j = tid; j < n; j += 256) m = fmaxf(m, row[j]);
    red[tid] = m; __syncthreads();
    #pragma unroll
    for (int s = 128; s > 0; s >>= 1) {
        if (tid < s) red[tid] = fmaxf(red[tid], red[tid + s]);
        __syncthreads();
    }
    m = red[0];
    __syncthreads();

    float sum = 0.0f;
    for (int j = tid; j < n; j += 256) sum += __expf(row[j] - m);
    red[tid] = sum; __syncthreads();
    #pragma unroll
    for (int s = 128; s > 0; s >>= 1) {
        if (tid < s) red[tid] += red[tid + s];
        __syncthreads();
    }
    float inv = 1.0f / red[0];

    for (int j = tid; j < n; j += 256) row[j] = __expf(row[j] - m) * inv;
    for (int j = n + tid; j < SEQ; j += 256) row[j] = 0.0f;  // masked region
}

// grid (E/128=8, S/128=16, B=4); causal trim: P rows in this tile are zero
// beyond column (bq+1)*128, so kEnd = (bq+1)*128.
__global__ __launch_bounds__(256, 2)
void out_kernel(float* __restrict__ out)
{
    int b = blockIdx.z;
    int bq = blockIdx.y;
    const float* Pb = g_P + (long long)b * SEQ * SEQ;
    const float* Vb = g_V + (long long)b * SEQ * EMB;
    float* Ob = out + (long long)b * SEQ * EMB;
    gemm_tile<false>(Pb, Vb, Ob, SEQ, EMB, EMB,
                     bq * BM, blockIdx.x * BN, (bq + 1) * BM, 1.0f);
}

// ---------------- launch ----------------

extern "C" void kernel_launch(void* const* d_in, const int* in_sizes, int n_in,
                              void* d_out, int out_size)
{
    const float* x  = (const float*)d_in[0];
    const float* Wq = (const float*)d_in[1];
    const float* Wk = (const float*)d_in[2];
    const float* Wv = (const float*)d_in[3];
    float* out = (float*)d_out;

    proj_kernel<<<dim3(KD / BN, (BATCH * SEQ) / BM, 3), 256>>>(x, Wq, Wk, Wv);
    scores_kernel<<<dim3(SEQ / BN, SEQ / BM, BATCH), 256>>>();
    softmax_kernel<<<dim3(SEQ, BATCH), 256>>>();
    out_kernel<<<dim3(EMB / BN, SEQ / BM, BATCH), 256>>>(out);
}

// round 2
// speedup vs baseline: 1.0009x; 1.0009x over previous
#include <cuda_runtime.h>
#include <math_constants.h>

// Problem constants
#define BATCH 4
#define SEQ   2048
#define EMB   1024
#define KD    1024

#define BM 128
#define BN 128
#define BK 16
#define LDSS 132   // BM + 4 pad: float4-aligned, near-conflict-free

// Static device scratch (allocation-free rule: __device__ globals are the workaround)
__device__ float g_Q[BATCH * SEQ * KD];            // 32 MB
__device__ float g_K[BATCH * SEQ * KD];            // 32 MB
__device__ float g_V[BATCH * SEQ * EMB];           // 32 MB
__device__ float g_P[(long long)BATCH * SEQ * SEQ]; // 64 MB (scores, then probs)

// C[m,n] = alpha * sum_k A[m,k] * Bop[k,n]
// TRANS_B = true : Bop[k,n] = B[n,k]  (B row-major [N,K])   -> NT GEMM
// TRANS_B = false: Bop[k,n] = B[k,n]  (B row-major [K,N])   -> NN GEMM
template<bool TRANS_B>
__device__ __forceinline__ void gemm_tile(
    const float* __restrict__ A, const float* __restrict__ B, float* __restrict__ C,
    int lda, int ldb, int ldc,
    int m0, int n0, int kEnd, float alpha)
{
    __shared__ __align__(16) float As[BK][LDSS];
    __shared__ __align__(16) float Bs[BK][LDSS];

    const int tid = threadIdx.x;
    const int tx = tid & 15;        // 0..15 -> column group
    const int ty = tid >> 4;        // 0..15 -> row group

    float acc[8][8];
    #pragma unroll
    for (int i = 0; i < 8; i++)
        #pragma unroll
        for (int j = 0; j < 8; j++) acc[i][j] = 0.0f;

    for (int k0 = 0; k0 < kEnd; k0 += BK) {
        // ---- load A tile [BM x BK], store transposed As[k][m] ----
        #pragma unroll
        for (int l = 0; l < 2; l++) {
            int f = tid + l * 256;           // float4 index, 512 total
            int row = f >> 2;                // 0..127
            int c4  = (f & 3) << 2;          // 0,4,8,12
            float4 v = *(const float4*)&A[(long long)(m0 + row) * lda + k0 + c4];
            As[c4 + 0][row] = v.x;
            As[c4 + 1][row] = v.y;
            As[c4 + 2][row] = v.z;
            As[c4 + 3][row] = v.w;
        }
        // ---- load B tile, store Bs[k][n] ----
        if (TRANS_B) {
            #pragma unroll
            for (int l = 0; l < 2; l++) {
                int f = tid + l * 256;
                int row = f >> 2;            // n index 0..127
                int c4  = (f & 3) << 2;      // k offset
                float4 v = *(const float4*)&B[(long long)(n0 + row) * ldb + k0 + c4];
                Bs[c4 + 0][row] = v.x;
                Bs[c4 + 1][row] = v.y;
                Bs[c4 + 2][row] = v.z;
                Bs[c4 + 3][row] = v.w;
            }
        } else {
            #pragma unroll
            for (int l = 0; l < 2; l++) {
                int f = tid + l * 256;
                int krow = f >> 5;           // 0..15
                int c4   = (f & 31) << 2;    // 0..124 step 4
                float4 v = *(const float4*)&B[(long long)(k0 + krow) * ldb + n0 + c4];
                *(float4*)&Bs[krow][c4] = v;
            }
        }
        __syncthreads();

        // ---- compute ----
        #pragma unroll
        for (int kk = 0; kk < BK; kk++) {
            float a[8], b[8];
            *(float4*)&a[0] = *(const float4*)&As[kk][ty * 4];
            *(float4*)&a[4] = *(const float4*)&As[kk][64 + ty * 4];
            *(float4*)&b[0] = *(const float4*)&Bs[kk][tx * 4];
            *(float4*)&b[4] = *(const float4*)&Bs[kk][64 + tx * 4];
            #pragma unroll
            for (int i = 0; i < 8; i++)
                #pragma unroll
                for (int j = 0; j < 8; j++)
                    acc[i][j] += a[i] * b[j];
        }
        __syncthreads();
    }

    // ---- epilogue ----
    #pragma unroll
    for (int i = 0; i < 8; i++) {
        int r = m0 + ((i < 4) ? (ty * 4 + i) : (64 + ty * 4 + (i - 4)));
        #pragma unroll
        for (int jj = 0; jj < 2; jj++) {
            float4 v;
            v.x = acc[i][jj * 4 + 0] * alpha;
            v.y = acc[i][jj * 4 + 1] * alpha;
            v.z = acc[i][jj * 4 + 2] * alpha;
            v.w = acc[i][jj * 4 + 3] * alpha;
            int c = n0 + tx * 4 + jj * 64;
            *(float4*)&C[(long long)r * ldc + c] = v;
        }
    }
}

// ---------------- kernels ----------------

// grid (N/128=8, M/128=64, 3), block 256
__global__ __launch_bounds__(256, 2)
void proj_kernel(const float* __restrict__ x,
                 const float* __restrict__ Wq,
                 const float* __restrict__ Wk,
                 const float* __restrict__ Wv)
{
    int z = blockIdx.z;
    const float* W = (z == 0) ? Wq : (z == 1) ? Wk : Wv;
    float* C = (z == 0) ? g_Q : (z == 1) ? g_K : g_V;
    gemm_tile<true>(x, W, C, EMB, EMB, KD,
                    blockIdx.y * BM, blockIdx.x * BN, EMB, 1.0f);
}

// grid (S/128=16, S/128=16, B=4): x = key tile, y = query tile
__global__ __launch_bounds__(256, 2)
void scores_kernel()
{
    int b = blockIdx.z;
    int bq = blockIdx.y, bs = blockIdx.x;
    if (bs > bq) return;  // strictly-upper tiles never read by softmax
    const float* Qb = g_Q + (long long)b * SEQ * KD;
    const float* Kb = g_K + (long long)b * SEQ * KD;
    float* Pb = g_P + (long long)b * SEQ * SEQ;
    gemm_tile<true>(Qb, Kb, Pb, KD, KD, SEQ,
                    bq * BM, bs * BN, KD, 0.03125f);  // 1/sqrt(1024)
}

// grid (SEQ, BATCH), block 256: causal row softmax, zero the masked tail
__global__ __launch_bounds__(256)
void softmax_kernel()
{
    int b = blockIdx.y, q = blockIdx.x;
    float* row = g_P + ((long long)b * SEQ + q) * SEQ;
    int n = q + 1;
    int tid = threadIdx.x;
    __shared__ float red[256];

    float m = -CUDART_INF_F;
    for (int j = tid; j < n; j += 256) m = fmaxf(m, row[j]);
    red[tid] = m; __syncthreads();
    #pragma unroll
    for (int s = 128; s > 0; s >>= 1) {
        if (tid < s) red[tid] = fmaxf(red[tid], red[tid + s]);
        __syncthreads();
    }
    m = red[0];
    __syncthreads();

    float sum = 0.0f;
    for (int j = tid; j < n; j += 256) sum += __expf(row[j] - m);
    red[tid] = sum; __syncthreads();
    #pragma unroll
    for (int s = 128; s > 0; s >>= 1) {
        if (tid < s) red[tid] += red[tid + s];
        __syncthreads();
    }
    float inv = 1.0f / red[0];

    for (int j = tid; j < n; j += 256) row[j] = __expf(row[j] - m) * inv;
    for (int j = n + tid; j < SEQ; j += 256) row[j] = 0.0f;  // masked region
}

// grid (E/128=8, S/128=16, B=4); causal trim: P rows in this tile are zero
// beyond column (bq+1)*128, so kEnd = (bq+1)*128.
__global__ __launch_bounds__(256, 2)
void out_kernel(float* __restrict__ out)
{
    int b = blockIdx.z;
    int bq = blockIdx.y;
    const float* Pb = g_P + (long long)b * SEQ * SEQ;
    const float* Vb = g_V + (long long)b * SEQ * EMB;
    float* Ob = out + (long long)b * SEQ * EMB;
    gemm_tile<false>(Pb, Vb, Ob, SEQ, EMB, EMB,
                     bq * BM, blockIdx.x * BN, (bq + 1) * BM, 1.0f);
}

// ---------------- launch ----------------

extern "C" void kernel_launch(void* const* d_in, const int* in_sizes, int n_in,
                              void* d_out, int out_size)
{
    const float* x  = (const float*)d_in[0];
    const float* Wq = (const float*)d_in[1];
    const float* Wk = (const float*)d_in[2];
    const float* Wv = (const float*)d_in[3];
    float* out = (float*)d_out;

    proj_kernel<<<dim3(KD / BN, (BATCH * SEQ) / BM, 3), 256>>>(x, Wq, Wk, Wv);
    scores_kernel<<<dim3(SEQ / BN, SEQ / BM, BATCH), 256>>>();
    softmax_kernel<<<dim3(SEQ, BATCH), 256>>>();
    out_kernel<<<dim3(EMB / BN, SEQ / BM, BATCH), 256>>>(out);
}

// round 3
// speedup vs baseline: 3.0069x; 3.0043x over previous
#include <cuda_runtime.h>
#include <math_constants.h>
#include <cstdint>

// Problem constants
#define BATCH 4
#define SEQ   2048
#define EMB   1024
#define KD    1024

// GEMM tile config
#define BM 128
#define BN 128
#define BKK 32
#define LDA_S 36      // smem row stride for [m][k] tiles (pad 4)
#define LDB_NN 132    // smem row stride for [k][n] tiles (pad 4)

#define SMEM_BYTES (2 * BM * LDA_S * 4 * 2)   // A + B(NT) double buffered = 73728

// Static device scratch
__device__ float g_Q[BATCH * SEQ * KD];
__device__ float g_K[BATCH * SEQ * KD];
__device__ float g_V[BATCH * SEQ * EMB];
__device__ float g_P[(long long)BATCH * SEQ * SEQ];

// ---------------- PTX helpers ----------------

__device__ __forceinline__ unsigned cvt_tf32(float x) {
    unsigned r;
    asm("cvt.rna.tf32.f32 %0, %1;" : "=r"(r) : "f"(x));
    return r;
}

__device__ __forceinline__ void mma_tf32(float d[4], const unsigned a[4], const unsigned b[2]) {
    asm volatile(
        "mma.sync.aligned.m16n8k8.row.col.f32.tf32.tf32.f32 "
        "{%0,%1,%2,%3}, {%4,%5,%6,%7}, {%8,%9}, {%0,%1,%2,%3};\n"
        : "+f"(d[0]), "+f"(d[1]), "+f"(d[2]), "+f"(d[3])
        : "r"(a[0]), "r"(a[1]), "r"(a[2]), "r"(a[3]), "r"(b[0]), "r"(b[1]));
}

__device__ __forceinline__ void cp_async16(uint32_t saddr, const void* gaddr) {
    asm volatile("cp.async.cg.shared.global [%0], [%1], 16;\n" :: "r"(saddr), "l"(gaddr));
}
#define CP_COMMIT() asm volatile("cp.async.commit_group;\n" ::: "memory")
#define CP_WAIT(n)  asm volatile("cp.async.wait_group %0;\n" :: "n"(n) : "memory")

// ---------------- GEMM core ----------------
// C[m,n] = alpha * sum_k A[m,k] * Bop[k,n]
// TRANS_B = true : Bop[k,n] = B[n,k]  (NT, B row-major [N,K])
// TRANS_B = false: Bop[k,n] = B[k,n]  (NN, B row-major [K,N])
template<bool TRANS_B>
__device__ __forceinline__ void gemm_mma(
    const float* __restrict__ A, const float* __restrict__ B, float* __restrict__ C,
    int lda, int ldb, int ldc, int m0, int n0, int kEnd, float alpha)
{
    extern __shared__ float sm[];
    float* As = sm;                      // [2][BM][LDA_S]
    float* Bs = sm + 2 * BM * LDA_S;     // NT: [2][BN][LDA_S]; NN: [2][BKK][LDB_NN]

    const int tid  = threadIdx.x;
    const int lane = tid & 31;
    const int warp = tid >> 5;
    const int wm   = warp & 1;           // 0..1 -> 64-row slab
    const int wn   = warp >> 1;          // 0..3 -> 32-col slab
    const int g    = lane >> 2;          // 0..7
    const int tg   = lane & 3;           // 0..3

    const uint32_t sAs = (uint32_t)__cvta_generic_to_shared(As);
    const uint32_t sBs = (uint32_t)__cvta_generic_to_shared(Bs);

    float acc[4][4][4];
    #pragma unroll
    for (int mt = 0; mt < 4; mt++)
        #pragma unroll
        for (int nt = 0; nt < 4; nt++)
            #pragma unroll
            for (int i = 0; i < 4; i++) acc[mt][nt][i] = 0.0f;

    const int nk = kEnd / BKK;

    // ---- tile loader (cp.async, 4 x 16B per thread per tile) ----
    auto load_tiles = [&](int stage, int k0) {
        // A tile: BM x BKK floats = 1024 16B chunks
        #pragma unroll
        for (int i = 0; i < 4; i++) {
            int c    = tid + i * 256;
            int row  = c >> 3;               // 0..127
            int col4 = (c & 7) << 2;         // 0..28
            cp_async16(sAs + (uint32_t)(((stage * BM + row) * LDA_S + col4) * 4),
                       &A[(long long)(m0 + row) * lda + k0 + col4]);
        }
        if (TRANS_B) {
            #pragma unroll
            for (int i = 0; i < 4; i++) {
                int c    = tid + i * 256;
                int row  = c >> 3;           // n index
                int col4 = (c & 7) << 2;     // k offset
                cp_async16(sBs + (uint32_t)(((stage * BN + row) * LDA_S + col4) * 4),
                           &B[(long long)(n0 + row) * ldb + k0 + col4]);
            }
        } else {
            #pragma unroll
            for (int i = 0; i < 4; i++) {
                int c    = tid + i * 256;
                int row  = c >> 5;           // k index 0..31
                int col4 = (c & 31) << 2;    // n offset
                cp_async16(sBs + (uint32_t)(((stage * BKK + row) * LDB_NN + col4) * 4),
                           &B[(long long)(k0 + row) * ldb + n0 + col4]);
            }
        }
    };

    load_tiles(0, 0);
    CP_COMMIT();

    for (int it = 0; it < nk; ++it) {
        if (it + 1 < nk) {
            load_tiles((it + 1) & 1, (it + 1) * BKK);
            CP_COMMIT();
            CP_WAIT(1);
        } else {
            CP_WAIT(0);
        }
        __syncthreads();

        const float* Asb = As + (it & 1) * BM * LDA_S;
        const float* Bsb = Bs + (it & 1) * (TRANS_B ? BN * LDA_S : BKK * LDB_NN);

        #pragma unroll
        for (int ks = 0; ks < 4; ks++) {
            const int k = ks * 8;
            unsigned af[4][4];
            #pragma unroll
            for (int mt = 0; mt < 4; mt++) {
                const float* p = Asb + (wm * 64 + mt * 16 + g) * LDA_S + k + tg;
                af[mt][0] = cvt_tf32(p[0]);
                af[mt][1] = cvt_tf32(p[8 * LDA_S]);
                af[mt][2] = cvt_tf32(p[4]);
                af[mt][3] = cvt_tf32(p[8 * LDA_S + 4]);
            }
            unsigned bf[4][2];
            #pragma unroll
            for (int nt = 0; nt < 4; nt++) {
                const int n = wn * 32 + nt * 8 + g;
                if (TRANS_B) {
                    const float* p = Bsb + n * LDA_S + k + tg;
                    bf[nt][0] = cvt_tf32(p[0]);
                    bf[nt][1] = cvt_tf32(p[4]);
                } else {
                    const float* p = Bsb + (k + tg) * LDB_NN + n;
                    bf[nt][0] = cvt_tf32(p[0]);
                    bf[nt][1] = cvt_tf32(p[4 * LDB_NN]);
                }
            }
            #pragma unroll
            for (int mt = 0; mt < 4; mt++)
                #pragma unroll
                for (int nt = 0; nt < 4; nt++)
                    mma_tf32(acc[mt][nt], af[mt], bf[nt]);
        }
        __syncthreads();
    }

    // ---- epilogue ----
    #pragma unroll
    for (int mt = 0; mt < 4; mt++) {
        const int r0 = m0 + wm * 64 + mt * 16 + g;
        const int r1 = r0 + 8;
        #pragma unroll
        for (int nt = 0; nt < 4; nt++) {
            const int cc = n0 + wn * 32 + nt * 8 + 2 * tg;
            float2 v0 = make_float2(acc[mt][nt][0] * alpha, acc[mt][nt][1] * alpha);
            float2 v1 = make_float2(acc[mt][nt][2] * alpha, acc[mt][nt][3] * alpha);
            *(float2*)&C[(long long)r0 * ldc + cc] = v0;
            *(float2*)&C[(long long)r1 * ldc + cc] = v1;
        }
    }
}

// ---------------- kernels ----------------

__global__ __launch_bounds__(256, 2)
void proj_kernel(const float* __restrict__ x,
                 const float* __restrict__ Wq,
                 const float* __restrict__ Wk,
                 const float* __restrict__ Wv)
{
    int z = blockIdx.z;
    const float* W = (z == 0) ? Wq : (z == 1) ? Wk : Wv;
    float* C = (z == 0) ? g_Q : (z == 1) ? g_K : g_V;
    gemm_mma<true>(x, W, C, EMB, EMB, KD,
                   blockIdx.y * BM, blockIdx.x * BN, EMB, 1.0f);
}

__global__ __launch_bounds__(256, 2)
void scores_kernel()
{
    int b = blockIdx.z;
    int bq = blockIdx.y, bs = blockIdx.x;
    if (bs > bq) return;  // strictly-upper tiles never read by softmax
    const float* Qb = g_Q + (long long)b * SEQ * KD;
    const float* Kb = g_K + (long long)b * SEQ * KD;
    float* Pb = g_P + (long long)b * SEQ * SEQ;
    gemm_mma<true>(Qb, Kb, Pb, KD, KD, SEQ,
                   bq * BM, bs * BN, KD, 0.03125f);
}

__global__ __launch_bounds__(256)
void softmax_kernel()
{
    int b = blockIdx.y, q = blockIdx.x;
    float* row = g_P + ((long long)b * SEQ + q) * SEQ;
    int n = q + 1;
    int tid = threadIdx.x;
    __shared__ float red[256];

    float m = -CUDART_INF_F;
    for (int j = tid; j < n; j += 256) m = fmaxf(m, row[j]);
    red[tid] = m; __syncthreads();
    #pragma unroll
    for (int s = 128; s > 0; s >>= 1) {
        if (tid < s) red[tid] = fmaxf(red[tid], red[tid + s]);
        __syncthreads();
    }
    m = red[0];
    __syncthreads();

    float sum = 0.0f;
    for (int j = tid; j < n; j += 256) sum += __expf(row[j] - m);
    red[tid] = sum; __syncthreads();
    #pragma unroll
    for (int s = 128; s > 0; s >>= 1) {
        if (tid < s) red[tid] += red[tid + s];
        __syncthreads();
    }
    float inv = 1.0f / red[0];

    for (int j = tid; j < n; j += 256) row[j] = __expf(row[j] - m) * inv;
    for (int j = n + tid; j < SEQ; j += 256) row[j] = 0.0f;
}

__global__ __launch_bounds__(256, 2)
void out_kernel(float* __restrict__ out)
{
    int b = blockIdx.z;
    int bq = blockIdx.y;
    const float* Pb = g_P + (long long)b * SEQ * SEQ;
    const float* Vb = g_V + (long long)b * SEQ * EMB;
    float* Ob = out + (long long)b * SEQ * EMB;
    gemm_mma<false>(Pb, Vb, Ob, SEQ, EMB, EMB,
                    bq * BM, blockIdx.x * BN, (bq + 1) * BM, 1.0f);
}

// ---------------- launch ----------------

extern "C" void kernel_launch(void* const* d_in, const int* in_sizes, int n_in,
                              void* d_out, int out_size)
{
    const float* x  = (const float*)d_in[0];
    const float* Wq = (const float*)d_in[1];
    const float* Wk = (const float*)d_in[2];
    const float* Wv = (const float*)d_in[3];
    float* out = (float*)d_out;

    cudaFuncSetAttribute(proj_kernel,   cudaFuncAttributeMaxDynamicSharedMemorySize, SMEM_BYTES);
    cudaFuncSetAttribute(scores_kernel, cudaFuncAttributeMaxDynamicSharedMemorySize, SMEM_BYTES);
    cudaFuncSetAttribute(out_kernel,    cudaFuncAttributeMaxDynamicSharedMemorySize, SMEM_BYTES);

    proj_kernel<<<dim3(KD / BN, (BATCH * SEQ) / BM, 3), 256, SMEM_BYTES>>>(x, Wq, Wk, Wv);
    scores_kernel<<<dim3(SEQ / BN, SEQ / BM, BATCH), 256, SMEM_BYTES>>>();
    softmax_kernel<<<dim3(SEQ, BATCH), 256>>>();
    out_kernel<<<dim3(EMB / BN, SEQ / BM, BATCH), 256, SMEM_BYTES>>>(out);
}

// round 5
// speedup vs baseline: 4.0513x; 1.3474x over previous
#include <cuda_runtime.h>
#include <math_constants.h>
#include <cstdint>

#define BATCH 4
#define SEQ   2048
#define EMB   1024
#define KD    1024

#define BM 128
#define BN 128
#define BKK 32                       // k per stage; 32 floats = 128B row

#define A_STG (BM * 128)             // 16 KB
#define B_STG (BN * 128)             // 16 KB
#define SM_B  (2 * A_STG)            // double-buffered A then B
#define SMEM_TOTAL 67584             // max(64KB pipeline, 128*132*4 transpose buf)

// ---------------- static device scratch ----------------
__device__ float g_x [BATCH * SEQ * EMB];
__device__ float g_Wq[KD * EMB];
__device__ float g_Wk[KD * EMB];
__device__ float g_Wv[EMB * EMB];
__device__ float g_Q [BATCH * SEQ * KD];
__device__ float g_K [BATCH * SEQ * KD];
__device__ float g_Vt[BATCH * EMB * SEQ];            // V transposed [b][e][s]
__device__ float g_P [(long long)BATCH * SEQ * SEQ];

// ---------------- helpers ----------------
__device__ __forceinline__ float tf32r(float x) {
    unsigned r; asm("cvt.rna.tf32.f32 %0, %1;" : "=r"(r) : "f"(x));
    return __uint_as_float(r);
}
__device__ __forceinline__ void cp_async16(uint32_t d, const void* g) {
    asm volatile("cp.async.cg.shared.global [%0], [%1], 16;\n" :: "r"(d), "l"(g));
}
#define CP_COMMIT() asm volatile("cp.async.commit_group;\n" ::: "memory")
#define CP_WAIT(n)  asm volatile("cp.async.wait_group %0;\n" :: "n"(n) : "memory")

__device__ __forceinline__ void ldsm_x4(uint32_t r[4], uint32_t addr) {
    asm volatile("ldmatrix.sync.aligned.m8n8.x4.shared.b16 {%0,%1,%2,%3}, [%4];"
        : "=r"(r[0]), "=r"(r[1]), "=r"(r[2]), "=r"(r[3]) : "r"(addr));
}
__device__ __forceinline__ void mma_tf32(float d[4], const uint32_t a[4], const uint32_t b[2]) {
    asm volatile(
        "mma.sync.aligned.m16n8k8.row.col.f32.tf32.tf32.f32 "
        "{%0,%1,%2,%3}, {%4,%5,%6,%7}, {%8,%9}, {%0,%1,%2,%3};\n"
        : "+f"(d[0]), "+f"(d[1]), "+f"(d[2]), "+f"(d[3])
        : "r"(a[0]), "r"(a[1]), "r"(a[2]), "r"(a[3]), "r"(b[0]), "r"(b[1]));
}

// ---------------- GEMM core: C[m,n] = alpha * A[m,:]·B[n,:], both K-major ----------------
// Inputs must be pre-rounded to tf32 bit patterns (no CVT in mainloop).
// EPI: 0 = store acc*alpha; 1 = store tf32r(acc); 2 = transposed tf32r store into Vt
template<int EPI>
__device__ __forceinline__ void gemm_core(
    const float* __restrict__ A, const float* __restrict__ B, float* __restrict__ C,
    int lda, int ldb, long long ldc, int m0, int n0, int kEnd, float alpha)
{
    extern __shared__ char smraw[];
    const uint32_t sb = (uint32_t)__cvta_generic_to_shared(smraw);
    const int tid  = threadIdx.x;
    const int lane = tid & 31;
    const int warp = tid >> 5;
    const int wm   = warp & 1;          // 64-row slab
    const int wn   = warp >> 1;         // 32-col slab
    const int g    = lane >> 2;         // 0..7
    const int tg   = lane & 3;          // 0..3

    // ldmatrix lane constants
    const int u  = lane & 7;
    const int j  = lane >> 3;
    const int c0A = j >> 1;             // k-chunk select for A matrices
    const int rA  = (j & 1) * 8 + u;    // row within 16-row tile
    const int c0B = j & 1;              // k-chunk select for B matrices
    const int nB  = (j >> 1) * 8 + u;   // n within 16-col group

    float acc[4][4][4];
    #pragma unroll
    for (int mt = 0; mt < 4; mt++)
        #pragma unroll
        for (int nt = 0; nt < 4; nt++)
            #pragma unroll
            for (int i = 0; i < 4; i++) acc[mt][nt][i] = 0.0f;

    const int nk = kEnd / BKK;

    auto load_stage = [&](int s, int k0) {
        #pragma unroll
        for (int i = 0; i < 4; i++) {            // A: 128 rows x 128B, sw128
            int c = tid + i * 256;
            int row = c >> 3, ch = c & 7;
            uint32_t sa = sb + (uint32_t)(s * A_STG + row * 128 + ((ch ^ (row & 7)) * 16));
            cp_async16(sa, &A[(long long)(m0 + row) * lda + k0 + ch * 4]);
        }
        #pragma unroll
        for (int i = 0; i < 4; i++) {            // B: 128 rows x 128B, sw128
            int c = tid + i * 256;
            int row = c >> 3, ch = c & 7;
            uint32_t sa = sb + (uint32_t)(SM_B + s * B_STG + row * 128 + ((ch ^ (row & 7)) * 16));
            cp_async16(sa, &B[(long long)(n0 + row) * ldb + k0 + ch * 4]);
        }
    };

    load_stage(0, 0);
    CP_COMMIT();

    for (int it = 0; it < nk; ++it) {
        if (it + 1 < nk) {
            load_stage((it + 1) & 1, (it + 1) * BKK);
            CP_COMMIT();
            CP_WAIT(1);
        } else {
            CP_WAIT(0);
        }
        __syncthreads();

        const uint32_t aBase = sb + (uint32_t)((it & 1) * A_STG);
        const uint32_t bBase = sb + (uint32_t)(SM_B + (it & 1) * B_STG);

        #pragma unroll
        for (int ks = 0; ks < 4; ks++) {
            uint32_t af[4][4], bf[2][4];
            #pragma unroll
            for (int mt = 0; mt < 4; mt++) {
                int row = wm * 64 + mt * 16 + rA;
                uint32_t addr = aBase + (uint32_t)(row * 128 + (((c0A + 2 * ks) ^ u) * 16));
                ldsm_x4(af[mt], addr);
            }
            #pragma unroll
            for (int h = 0; h < 2; h++) {
                int n = wn * 32 + h * 16 + nB;
                uint32_t addr = bBase + (uint32_t)(n * 128 + (((c0B + 2 * ks) ^ u) * 16));
                ldsm_x4(bf[h], addr);
            }
            #pragma unroll
            for (int mt = 0; mt < 4; mt++)
                #pragma unroll
                for (int nt = 0; nt < 4; nt++)
                    mma_tf32(acc[mt][nt], af[mt], &bf[nt >> 1][(nt & 1) * 2]);
        }
        __syncthreads();
    }

    // ---- epilogue ----
    if (EPI == 2) {
        // transpose 128x128 tile through smem, store coalesced into Vt[e][s]
        float* sT = (float*)smraw;               // [128 cols(e)][132]
        #pragma unroll
        for (int mt = 0; mt < 4; mt++)
            #pragma unroll
            for (int nt = 0; nt < 4; nt++)
                #pragma unroll
                for (int i = 0; i < 4; i++) {
                    int rl = wm * 64 + mt * 16 + g + (i >> 1) * 8;
                    int cl = wn * 32 + nt * 8 + 2 * tg + (i & 1);
                    sT[cl * 132 + rl] = tf32r(acc[mt][nt][i]);
                }
        __syncthreads();
        int b  = m0 >> 11;
        int s0 = m0 & 2047;
        float* dst = C + ((long long)b * EMB + n0) * (long long)SEQ + s0;
        #pragma unroll
        for (int i = 0; i < 16; i++) {
            int idx = tid + i * 256;
            int er = idx >> 5, sc = (idx & 31) * 4;
            float4 v = *(const float4*)&sT[er * 132 + sc];
            *(float4*)&dst[(long long)er * SEQ + sc] = v;
        }
        __syncthreads();
    } else {
        #pragma unroll
        for (int mt = 0; mt < 4; mt++) {
            const long long r0 = m0 + wm * 64 + mt * 16 + g;
            const long long r1 = r0 + 8;
            #pragma unroll
            for (int nt = 0; nt < 4; nt++) {
                const int cc = n0 + wn * 32 + nt * 8 + 2 * tg;
                float2 v0, v1;
                if (EPI == 1) {
                    v0 = make_float2(tf32r(acc[mt][nt][0]), tf32r(acc[mt][nt][1]));
                    v1 = make_float2(tf32r(acc[mt][nt][2]), tf32r(acc[mt][nt][3]));
                } else {
                    v0 = make_float2(acc[mt][nt][0] * alpha, acc[mt][nt][1] * alpha);
                    v1 = make_float2(acc[mt][nt][2] * alpha, acc[mt][nt][3] * alpha);
                }
                *(float2*)&C[r0 * ldc + cc] = v0;
                *(float2*)&C[r1 * ldc + cc] = v1;
            }
        }
    }
}

// ---------------- kernels ----------------

__global__ void round_kernel(const float* __restrict__ src, int which, int n4) {
    int i = blockIdx.x * blockDim.x + threadIdx.x;
    if (i >= n4) return;
    float* dst = (which == 0) ? g_x : (which == 1) ? g_Wq : (which == 2) ? g_Wk : g_Wv;
    float4 v = ((const float4*)src)[i];
    v.x = tf32r(v.x); v.y = tf32r(v.y); v.z = tf32r(v.z); v.w = tf32r(v.w);
    ((float4*)dst)[i] = v;
}

// grid (8, 64, 3)
__global__ __launch_bounds__(256, 2)
void proj_kernel()
{
    int z = blockIdx.z;
    const float* W = (z == 0) ? g_Wq : (z == 1) ? g_Wk : g_Wv;
    if (z == 2)
        gemm_core<2>(g_x, W, g_Vt, EMB, EMB, 0,
                     blockIdx.y * BM, blockIdx.x * BN, EMB, 1.0f);
    else
        gemm_core<1>(g_x, W, (z == 0) ? g_Q : g_K, EMB, EMB, KD,
                     blockIdx.y * BM, blockIdx.x * BN, EMB, 1.0f);
}

// grid (16, 16, 4); skip fully-masked tiles
__global__ __launch_bounds__(256, 2)
void scores_kernel()
{
    int b = blockIdx.z, bq = blockIdx.y, bs = blockIdx.x;
    if (bs > bq) return;
    gemm_core<0>(g_Q + (long long)b * SEQ * KD, g_K + (long long)b * SEQ * KD,
                 g_P + (long long)b * SEQ * SEQ, KD, KD, SEQ,
                 bq * BM, bs * BN, KD, 0.03125f);
}

__global__ __launch_bounds__(256)
void softmax_kernel()
{
    __shared__ float sr[SEQ];
    __shared__ float red[256];
    int b = blockIdx.y, q = blockIdx.x, tid = threadIdx.x;
    float* row = g_P + ((long long)b * SEQ + q) * SEQ;
    int n = q + 1;

    float m = -CUDART_INF_F;
    for (int jx = tid; jx < n; jx += 256) { float v = row[jx]; sr[jx] = v; m = fmaxf(m, v); }
    red[tid] = m; __syncthreads();
    #pragma unroll
    for (int s = 128; s > 0; s >>= 1) {
        if (tid < s) red[tid] = fmaxf(red[tid], red[tid + s]);
        __syncthreads();
    }
    m = red[0];
    __syncthreads();

    float sum = 0.0f;
    for (int jx = tid; jx < n; jx += 256) { float e = __expf(sr[jx] - m); sr[jx] = e; sum += e; }
    red[tid] = sum; __syncthreads();
    #pragma unroll
    for (int s = 128; s > 0; s >>= 1) {
        if (tid < s) red[tid] += red[tid + s];
        __syncthreads();
    }
    float inv = 1.0f / red[0];

    for (int jx = tid; jx < n; jx += 256) row[jx] = tf32r(sr[jx] * inv);
    for (int jx = n + tid; jx < SEQ; jx += 256) row[jx] = 0.0f;
}

// grid (8, 16, 4); causal k-trim
__global__ __launch_bounds__(256, 2)
void out_kernel(float* __restrict__ out)
{
    int b = blockIdx.z, bq = blockIdx.y;
    gemm_core<0>(g_P + (long long)b * SEQ * SEQ, g_Vt + (long long)b * EMB * SEQ,
                 out + (long long)b * SEQ * EMB, SEQ, SEQ, EMB,
                 bq * BM, blockIdx.x * BN, (bq + 1) * BM, 1.0f);
}

// ---------------- launch ----------------
extern "C" void kernel_launch(void* const* d_in, const int* in_sizes, int n_in,
                              void* d_out, int out_size)
{
    const float* x  = (const float*)d_in[0];
    const float* Wq = (const float*)d_in[1];
    const float* Wk = (const float*)d_in[2];
    const float* Wv = (const float*)d_in[3];
    float* out = (float*)d_out;

    cudaFuncSetAttribute(proj_kernel,   cudaFuncAttributeMaxDynamicSharedMemorySize, SMEM_TOTAL);
    cudaFuncSetAttribute(scores_kernel, cudaFuncAttributeMaxDynamicSharedMemorySize, SMEM_TOTAL);
    cudaFuncSetAttribute(out_kernel,    cudaFuncAttributeMaxDynamicSharedMemorySize, SMEM_TOTAL);

    round_kernel<<<(BATCH * SEQ * EMB / 4 + 255) / 256, 256>>>(x, 0, BATCH * SEQ * EMB / 4);
    round_kernel<<<(KD * EMB / 4 + 255) / 256, 256>>>(Wq, 1, KD * EMB / 4);
    round_kernel<<<(KD * EMB / 4 + 255) / 256, 256>>>(Wk, 2, KD * EMB / 4);
    round_kernel<<<(EMB * EMB / 4 + 255) / 256, 256>>>(Wv, 3, EMB * EMB / 4);

    proj_kernel<<<dim3(KD / BN, (BATCH * SEQ) / BM, 3), 256, SMEM_TOTAL>>>();
    scores_kernel<<<dim3(SEQ / BN, SEQ / BM, BATCH), 256, SMEM_TOTAL>>>();
    softmax_kernel<<<dim3(SEQ, BATCH), 256>>>();
    out_kernel<<<dim3(EMB / BN, SEQ / BM, BATCH), 256, SMEM_TOTAL>>>(out);
}